// round 1
// baseline (speedup 1.0000x reference)
#include <cuda_runtime.h>

#define BB   4
#define CC   256
#define NN   1024
#define HH   8
#define DD   256
#define DVV  256
#define BHH  32     // BB*HH

#define TILE 64
#define KCH  16
#define LDP  68     // TILE + 4 pad

// Scratch (static __device__ arrays; no allocation at runtime)
__device__ float g_QT[BHH * NN * DD];     // [bh][n][d]   33.5 MB
__device__ float g_KT[BHH * NN * DD];     // [bh][n][d]   33.5 MB
__device__ float g_V [BHH * DVV * NN];    // [bh][d][n]   33.5 MB
__device__ float g_YP[BB * DVV * NN];     // [b][d][n]     4 MB
__device__ float g_S [BHH * NN * NN];     // [bh][i][j]  134 MB

// ---------------------------------------------------------------------------
// Projection GEMM: Out[o][n] = sum_c W[o][c] * X[b][c][n] + bias[o]
// mode 0: store head-transposed  -> Out[((b*H + o/D)*N + n)*D + o%D]  (Q,K)
// mode 1: store natural          -> Out[(b*Orows + o)*N + n]          (V,YP)
// ---------------------------------------------------------------------------
__global__ __launch_bounds__(256)
void proj_kernel(const float* __restrict__ W, const float* __restrict__ bias,
                 const float* __restrict__ X, float* __restrict__ Out,
                 int Orows, int mode)
{
    __shared__ float As[KCH][LDP];  // W chunk, transposed: As[k][o]
    __shared__ float Bs[KCH][LDP];  // X chunk: Bs[k][n]

    const int b  = blockIdx.z;
    const int ob = blockIdx.y * TILE;
    const int nb = blockIdx.x * TILE;
    const int t  = threadIdx.x;

    const int ali = t >> 2;          // 0..63  (o row for A load)
    const int alk = (t & 3) << 2;    // 0,4,8,12
    const int blk = t >> 4;          // 0..15  (k row for B load)
    const int bln = (t & 15) << 2;   // 0..60
    const int i0  = (t & 15) << 2;   // micro-tile o base
    const int j0  = (t >> 4) << 2;   // micro-tile n base

    const float* Xb = X + (size_t)b * CC * NN;
    float acc[4][4] = {};

    for (int kc = 0; kc < CC; kc += KCH) {
        float4 av = *(const float4*)(W  + (size_t)(ob + ali) * CC + kc + alk);
        float4 bv = *(const float4*)(Xb + (size_t)(kc + blk) * NN + nb + bln);
        __syncthreads();
        As[alk + 0][ali] = av.x; As[alk + 1][ali] = av.y;
        As[alk + 2][ali] = av.z; As[alk + 3][ali] = av.w;
        *(float4*)&Bs[blk][bln] = bv;
        __syncthreads();
#pragma unroll
        for (int k = 0; k < KCH; ++k) {
            float4 a  = *(const float4*)&As[k][i0];
            float4 b4 = *(const float4*)&Bs[k][j0];
            acc[0][0] += a.x * b4.x; acc[0][1] += a.x * b4.y;
            acc[0][2] += a.x * b4.z; acc[0][3] += a.x * b4.w;
            acc[1][0] += a.y * b4.x; acc[1][1] += a.y * b4.y;
            acc[1][2] += a.y * b4.z; acc[1][3] += a.y * b4.w;
            acc[2][0] += a.z * b4.x; acc[2][1] += a.z * b4.y;
            acc[2][2] += a.z * b4.z; acc[2][3] += a.z * b4.w;
            acc[3][0] += a.w * b4.x; acc[3][1] += a.w * b4.y;
            acc[3][2] += a.w * b4.z; acc[3][3] += a.w * b4.w;
        }
    }

    float bv0 = 0.f, bv1 = 0.f, bv2 = 0.f, bv3 = 0.f;
    if (bias) {
        bv0 = bias[ob + i0 + 0]; bv1 = bias[ob + i0 + 1];
        bv2 = bias[ob + i0 + 2]; bv3 = bias[ob + i0 + 3];
    }

    if (mode == 0) {
        const int og0  = ob + i0;           // global o; 4 consecutive o in same head
        const int h    = og0 / DD;
        const int dloc = og0 % DD;
        const size_t base = (size_t)(b * HH + h) * NN * DD;
#pragma unroll
        for (int jj = 0; jj < 4; ++jj) {
            const int n = nb + j0 + jj;
            float4 vv = make_float4(acc[0][jj] + bv0, acc[1][jj] + bv1,
                                    acc[2][jj] + bv2, acc[3][jj] + bv3);
            *(float4*)(Out + base + (size_t)n * DD + dloc) = vv;
        }
    } else {
#pragma unroll
        for (int ii = 0; ii < 4; ++ii) {
            const int og = ob + i0 + ii;
            const float bvi = (ii == 0) ? bv0 : (ii == 1) ? bv1 : (ii == 2) ? bv2 : bv3;
            float4 vv = make_float4(acc[ii][0] + bvi, acc[ii][1] + bvi,
                                    acc[ii][2] + bvi, acc[ii][3] + bvi);
            *(float4*)(Out + (size_t)(b * Orows + og) * NN + nb + j0) = vv;
        }
    }
}

// ---------------------------------------------------------------------------
// Batched NT GEMM: C[z][i][j] = sum_k A[z][i][k] * B[z][j][k]
// Both operands k-contiguous (row length == K). ldc == NN for both uses.
// mode 0: plain store (energy S)
// mode 1: attention epilogue: out = (g*acc + yp) / (1+g), per-head gamma
// ---------------------------------------------------------------------------
__global__ __launch_bounds__(256)
void gemm_nt_kernel(const float* __restrict__ A, const float* __restrict__ Bm,
                    float* __restrict__ Cm, int K,
                    size_t sA, size_t sB, size_t sC, int mode,
                    const float* __restrict__ gamma, const float* __restrict__ YP)
{
    __shared__ float As[KCH][LDP];
    __shared__ float Bs[KCH][LDP];

    const int z  = blockIdx.z;
    const int ib = blockIdx.y * TILE;
    const int jb = blockIdx.x * TILE;
    const int t  = threadIdx.x;

    const int li = t >> 2;
    const int lk = (t & 3) << 2;
    const int i0 = (t & 15) << 2;
    const int j0 = (t >> 4) << 2;

    const float* Ab = A  + (size_t)z * sA;
    const float* Bp = Bm + (size_t)z * sB;
    float acc[4][4] = {};

    for (int kc = 0; kc < K; kc += KCH) {
        float4 av = *(const float4*)(Ab + (size_t)(ib + li) * K + kc + lk);
        float4 bv = *(const float4*)(Bp + (size_t)(jb + li) * K + kc + lk);
        __syncthreads();
        As[lk + 0][li] = av.x; As[lk + 1][li] = av.y;
        As[lk + 2][li] = av.z; As[lk + 3][li] = av.w;
        Bs[lk + 0][li] = bv.x; Bs[lk + 1][li] = bv.y;
        Bs[lk + 2][li] = bv.z; Bs[lk + 3][li] = bv.w;
        __syncthreads();
#pragma unroll
        for (int k = 0; k < KCH; ++k) {
            float4 a  = *(const float4*)&As[k][i0];
            float4 b4 = *(const float4*)&Bs[k][j0];
            acc[0][0] += a.x * b4.x; acc[0][1] += a.x * b4.y;
            acc[0][2] += a.x * b4.z; acc[0][3] += a.x * b4.w;
            acc[1][0] += a.y * b4.x; acc[1][1] += a.y * b4.y;
            acc[1][2] += a.y * b4.z; acc[1][3] += a.y * b4.w;
            acc[2][0] += a.z * b4.x; acc[2][1] += a.z * b4.y;
            acc[2][2] += a.z * b4.z; acc[2][3] += a.z * b4.w;
            acc[3][0] += a.w * b4.x; acc[3][1] += a.w * b4.y;
            acc[3][2] += a.w * b4.z; acc[3][3] += a.w * b4.w;
        }
    }

    float* Cb = Cm + (size_t)z * sC;
    if (mode == 0) {
#pragma unroll
        for (int ii = 0; ii < 4; ++ii) {
            *(float4*)(Cb + (size_t)(ib + i0 + ii) * NN + jb + j0) =
                make_float4(acc[ii][0], acc[ii][1], acc[ii][2], acc[ii][3]);
        }
    } else {
        const int h = z & (HH - 1);
        const int b = z >> 3;
        const float g  = gamma[h];
        const float sa = g / (1.0f + g);
        const float sb = 1.0f / (1.0f + g);
        const float* ypb = YP + (size_t)b * DVV * NN;
#pragma unroll
        for (int ii = 0; ii < 4; ++ii) {
            const int d = ib + i0 + ii;
            float4 yv = *(const float4*)(ypb + (size_t)d * NN + jb + j0);
            float4 vv = make_float4(sa * acc[ii][0] + sb * yv.x,
                                    sa * acc[ii][1] + sb * yv.y,
                                    sa * acc[ii][2] + sb * yv.z,
                                    sa * acc[ii][3] + sb * yv.w);
            *(float4*)(Cb + (size_t)d * NN + jb + j0) = vv;
        }
    }
}

// ---------------------------------------------------------------------------
// Row softmax over S: one warp per row of 1024 floats, in-place.
// ---------------------------------------------------------------------------
__global__ __launch_bounds__(256)
void softmax_kernel(float* __restrict__ S)
{
    const int warp = threadIdx.x >> 5;
    const int lane = threadIdx.x & 31;
    const size_t row = (size_t)blockIdx.x * 8 + warp;
    float* r = S + row * NN;

    float4 v[8];
    float mx = -3.0e38f;
#pragma unroll
    for (int q = 0; q < 8; ++q) {
        v[q] = *(const float4*)(r + q * 128 + lane * 4);
        mx = fmaxf(mx, fmaxf(fmaxf(v[q].x, v[q].y), fmaxf(v[q].z, v[q].w)));
    }
#pragma unroll
    for (int o = 16; o > 0; o >>= 1)
        mx = fmaxf(mx, __shfl_xor_sync(0xffffffffu, mx, o));

    float sum = 0.f;
#pragma unroll
    for (int q = 0; q < 8; ++q) {
        v[q].x = __expf(v[q].x - mx); v[q].y = __expf(v[q].y - mx);
        v[q].z = __expf(v[q].z - mx); v[q].w = __expf(v[q].w - mx);
        sum += (v[q].x + v[q].y) + (v[q].z + v[q].w);
    }
#pragma unroll
    for (int o = 16; o > 0; o >>= 1)
        sum += __shfl_xor_sync(0xffffffffu, sum, o);

    const float inv = 1.0f / sum;
#pragma unroll
    for (int q = 0; q < 8; ++q) {
        v[q].x *= inv; v[q].y *= inv; v[q].z *= inv; v[q].w *= inv;
        *(float4*)(r + q * 128 + lane * 4) = v[q];
    }
}

// ---------------------------------------------------------------------------
extern "C" void kernel_launch(void* const* d_in, const int* in_sizes, int n_in,
                              void* d_out, int out_size)
{
    const float* x     = (const float*)d_in[0];
    const float* y     = (const float*)d_in[1];
    const float* Wq    = (const float*)d_in[2];
    const float* bq    = (const float*)d_in[3];
    const float* Wk    = (const float*)d_in[4];
    const float* bk    = (const float*)d_in[5];
    const float* Wv    = (const float*)d_in[6];
    const float* bv    = (const float*)d_in[7];
    const float* Wp    = (const float*)d_in[8];
    const float* gamma = (const float*)d_in[9];
    float* out = (float*)d_out;

    float *QT, *KT, *V, *YP, *S;
    cudaGetSymbolAddress((void**)&QT, g_QT);
    cudaGetSymbolAddress((void**)&KT, g_KT);
    cudaGetSymbolAddress((void**)&V,  g_V);
    cudaGetSymbolAddress((void**)&YP, g_YP);
    cudaGetSymbolAddress((void**)&S,  g_S);

    dim3 thr(256);

    // Projections
    proj_kernel<<<dim3(NN / TILE, (HH * DD)  / TILE, BB), thr>>>(Wq, bq, x, QT, HH * DD, 0);
    proj_kernel<<<dim3(NN / TILE, (HH * DD)  / TILE, BB), thr>>>(Wk, bk, x, KT, HH * DD, 0);
    proj_kernel<<<dim3(NN / TILE, (HH * DVV) / TILE, BB), thr>>>(Wv, bv, y, V,  HH * DVV, 1);
    proj_kernel<<<dim3(NN / TILE, DVV / TILE, BB), thr>>>(Wp, nullptr, y, YP, DVV, 1);

    // S[bh][i][j] = sum_d Q[bh][i][d] * K[bh][j][d]
    gemm_nt_kernel<<<dim3(NN / TILE, NN / TILE, BHH), thr>>>(
        QT, KT, S, DD,
        (size_t)NN * DD, (size_t)NN * DD, (size_t)NN * NN,
        0, nullptr, nullptr);

    // softmax over keys (rows of S)
    softmax_kernel<<<dim3(BHH * NN / 8), thr>>>(S);

    // out[bh][d][n] = sum_m V[bh][d][m] * P[bh][n][m], fused residual epilogue
    gemm_nt_kernel<<<dim3(NN / TILE, DVV / TILE, BHH), thr>>>(
        V, S, out, NN,
        (size_t)DVV * NN, (size_t)NN * NN, (size_t)DVV * NN,
        1, gamma, YP);
}

// round 2
// speedup vs baseline: 2.2704x; 2.2704x over previous
#include <cuda_runtime.h>
#include <cuda_bf16.h>
#include <cstdint>

#define BB   4
#define CC   256
#define NN   1024
#define HH   8
#define DD   256
#define DVV  256
#define BHH  32     // BB*HH

// ---- proj tiling ----
#define TILE 64
#define KCH  16
#define LDP  68

// ---- tensor GEMM tiling ----
#define BM   128
#define BN   128
#define BK   32
#define SKP  40     // padded smem row (bf16 elems): stride 20 words, conflict-free

// Scratch (static __device__ arrays; no runtime allocation)
__device__ __nv_bfloat16 g_Qh[BHH * NN * DD];
__device__ __nv_bfloat16 g_Ql[BHH * NN * DD];
__device__ __nv_bfloat16 g_Kb[BHH * NN * DD];
__device__ __nv_bfloat16 g_Vb[BHH * DVV * NN];
__device__ float         g_YP[BB * DVV * NN];
__device__ float         g_S [BHH * NN * NN];
__device__ __nv_bfloat16 g_P [BHH * NN * NN];

// ---------------------------------------------------------------------------
// PTX wrappers
// ---------------------------------------------------------------------------
__device__ __forceinline__ void ldm_x4(uint32_t& r0, uint32_t& r1, uint32_t& r2,
                                       uint32_t& r3, uint32_t addr) {
    asm volatile("ldmatrix.sync.aligned.m8n8.x4.shared.b16 {%0,%1,%2,%3}, [%4];\n"
                 : "=r"(r0), "=r"(r1), "=r"(r2), "=r"(r3) : "r"(addr));
}
__device__ __forceinline__ void mma_bf16(float* c, const uint32_t* a, const uint32_t* b) {
    asm volatile("mma.sync.aligned.m16n8k16.row.col.f32.bf16.bf16.f32 "
                 "{%0,%1,%2,%3}, {%4,%5,%6,%7}, {%8,%9}, {%0,%1,%2,%3};\n"
                 : "+f"(c[0]), "+f"(c[1]), "+f"(c[2]), "+f"(c[3])
                 : "r"(a[0]), "r"(a[1]), "r"(a[2]), "r"(a[3]), "r"(b[0]), "r"(b[1]));
}

// ---------------------------------------------------------------------------
// Projection GEMM: Out[o][n] = sum_c W[o][c] * X[b][c][n] + bias[o]
// mode 0: head-transposed bf16 hi/lo -> OutA/OutB at [bh][n][d]   (Q)
// mode 3: head-transposed bf16       -> OutA at [bh][n][d]        (K)
// mode 1: natural bf16               -> OutA at [b][o][n]         (V)
// mode 2: natural fp32               -> OutA at [b][o][n]         (YP)
// ---------------------------------------------------------------------------
__global__ __launch_bounds__(256)
void proj_kernel(const float* __restrict__ W, const float* __restrict__ bias,
                 const float* __restrict__ X, void* __restrict__ OutA,
                 void* __restrict__ OutB, int Orows, int mode)
{
    __shared__ float As[KCH][LDP];
    __shared__ float Bs[KCH][LDP];

    const int b  = blockIdx.z;
    const int ob = blockIdx.y * TILE;
    const int nb = blockIdx.x * TILE;
    const int t  = threadIdx.x;

    const int ali = t >> 2;
    const int alk = (t & 3) << 2;
    const int blk = t >> 4;
    const int bln = (t & 15) << 2;
    const int i0  = (t & 15) << 2;
    const int j0  = (t >> 4) << 2;

    const float* Xb = X + (size_t)b * CC * NN;
    float acc[4][4] = {};

    for (int kc = 0; kc < CC; kc += KCH) {
        float4 av = *(const float4*)(W  + (size_t)(ob + ali) * CC + kc + alk);
        float4 bv = *(const float4*)(Xb + (size_t)(kc + blk) * NN + nb + bln);
        __syncthreads();
        As[alk + 0][ali] = av.x; As[alk + 1][ali] = av.y;
        As[alk + 2][ali] = av.z; As[alk + 3][ali] = av.w;
        *(float4*)&Bs[blk][bln] = bv;
        __syncthreads();
#pragma unroll
        for (int k = 0; k < KCH; ++k) {
            float4 a  = *(const float4*)&As[k][i0];
            float4 b4 = *(const float4*)&Bs[k][j0];
            acc[0][0] += a.x * b4.x; acc[0][1] += a.x * b4.y;
            acc[0][2] += a.x * b4.z; acc[0][3] += a.x * b4.w;
            acc[1][0] += a.y * b4.x; acc[1][1] += a.y * b4.y;
            acc[1][2] += a.y * b4.z; acc[1][3] += a.y * b4.w;
            acc[2][0] += a.z * b4.x; acc[2][1] += a.z * b4.y;
            acc[2][2] += a.z * b4.z; acc[2][3] += a.z * b4.w;
            acc[3][0] += a.w * b4.x; acc[3][1] += a.w * b4.y;
            acc[3][2] += a.w * b4.z; acc[3][3] += a.w * b4.w;
        }
    }

    float bv0 = 0.f, bv1 = 0.f, bv2 = 0.f, bv3 = 0.f;
    if (bias) {
        bv0 = bias[ob + i0 + 0]; bv1 = bias[ob + i0 + 1];
        bv2 = bias[ob + i0 + 2]; bv3 = bias[ob + i0 + 3];
    }

    if (mode == 0 || mode == 3) {
        __nv_bfloat16* Oh = (__nv_bfloat16*)OutA;
        __nv_bfloat16* Ol = (__nv_bfloat16*)OutB;
        const int og0  = ob + i0;
        const int h    = og0 / DD;
        const int dloc = og0 % DD;
        const size_t base = (size_t)(b * HH + h) * NN * DD;
#pragma unroll
        for (int jj = 0; jj < 4; ++jj) {
            const int n = nb + j0 + jj;
            float4 vv = make_float4(acc[0][jj] + bv0, acc[1][jj] + bv1,
                                    acc[2][jj] + bv2, acc[3][jj] + bv3);
            __nv_bfloat162 h0 = __float22bfloat162_rn(make_float2(vv.x, vv.y));
            __nv_bfloat162 h1 = __float22bfloat162_rn(make_float2(vv.z, vv.w));
            __nv_bfloat162* ph = (__nv_bfloat162*)(Oh + base + (size_t)n * DD + dloc);
            ph[0] = h0; ph[1] = h1;
            if (mode == 0) {
                __nv_bfloat162 l0 = __float22bfloat162_rn(make_float2(
                    vv.x - __bfloat162float(h0.x), vv.y - __bfloat162float(h0.y)));
                __nv_bfloat162 l1 = __float22bfloat162_rn(make_float2(
                    vv.z - __bfloat162float(h1.x), vv.w - __bfloat162float(h1.y)));
                __nv_bfloat162* pl = (__nv_bfloat162*)(Ol + base + (size_t)n * DD + dloc);
                pl[0] = l0; pl[1] = l1;
            }
        }
    } else if (mode == 1) {
        __nv_bfloat16* Ov = (__nv_bfloat16*)OutA;
#pragma unroll
        for (int ii = 0; ii < 4; ++ii) {
            const int og = ob + i0 + ii;
            const float bvi = (ii == 0) ? bv0 : (ii == 1) ? bv1 : (ii == 2) ? bv2 : bv3;
            __nv_bfloat162 v0 = __float22bfloat162_rn(
                make_float2(acc[ii][0] + bvi, acc[ii][1] + bvi));
            __nv_bfloat162 v1 = __float22bfloat162_rn(
                make_float2(acc[ii][2] + bvi, acc[ii][3] + bvi));
            __nv_bfloat162* po = (__nv_bfloat162*)(Ov + (size_t)(b * Orows + og) * NN + nb + j0);
            po[0] = v0; po[1] = v1;
        }
    } else {
        float* Of = (float*)OutA;
#pragma unroll
        for (int ii = 0; ii < 4; ++ii) {
            const int og = ob + i0 + ii;
            float4 vv = make_float4(acc[ii][0], acc[ii][1], acc[ii][2], acc[ii][3]);
            *(float4*)(Of + (size_t)(b * Orows + og) * NN + nb + j0) = vv;
        }
    }
}

// ---------------------------------------------------------------------------
// GEMM1: S[z][i][j] = sum_d (Qh+Ql)[z][i][d] * K[z][j][d]   (2-pass bf16 MMA)
// ---------------------------------------------------------------------------
__global__ __launch_bounds__(256)
void gemm_qk(const __nv_bfloat16* __restrict__ Qh, const __nv_bfloat16* __restrict__ Ql,
             const __nv_bfloat16* __restrict__ Kb, float* __restrict__ S)
{
    __shared__ __align__(16) __nv_bfloat16 As[2][BM][SKP];  // [plane][row i][k]
    __shared__ __align__(16) __nv_bfloat16 Bs[BN][SKP];     // [row j][k]

    const int z  = blockIdx.z;
    const int ib = blockIdx.y * BM;
    const int jb = blockIdx.x * BN;
    const int t  = threadIdx.x;
    const int lane = t & 31, warp = t >> 5;
    const int wm = warp >> 2, wn = warp & 3;   // warp tile 64(m) x 32(n)

    const int rowA = t >> 2;           // 0..63
    const int cc   = (t & 3) << 3;     // bf16 col chunk

    const size_t zq = (size_t)z * NN * DD;
    const __nv_bfloat16* pQh0 = Qh + zq + (size_t)(ib + rowA) * DD + cc;
    const __nv_bfloat16* pQh1 = pQh0 + (size_t)64 * DD;
    const __nv_bfloat16* pQl0 = Ql + zq + (size_t)(ib + rowA) * DD + cc;
    const __nv_bfloat16* pQl1 = pQl0 + (size_t)64 * DD;
    const __nv_bfloat16* pK0  = Kb + zq + (size_t)(jb + rowA) * DD + cc;
    const __nv_bfloat16* pK1  = pK0 + (size_t)64 * DD;

    uint32_t aBase = (uint32_t)__cvta_generic_to_shared(&As[0][0][0]);
    uint32_t bBase = (uint32_t)__cvta_generic_to_shared(&Bs[0][0]);

    const int aRow = lane & 15;
    const int aKh  = (lane >> 4) << 3;
    const int bRow = ((lane >> 4) << 3) + (lane & 7);
    const int bKh  = ((lane >> 3) & 1) << 3;

    float acc[4][4][4] = {};

    uint4 sQh0 = *(const uint4*)pQh0, sQh1 = *(const uint4*)pQh1;
    uint4 sQl0 = *(const uint4*)pQl0, sQl1 = *(const uint4*)pQl1;
    uint4 sK0  = *(const uint4*)pK0,  sK1  = *(const uint4*)pK1;

    for (int it = 0; it < DD / BK; ++it) {
        __syncthreads();
        *(uint4*)&As[0][rowA     ][cc] = sQh0;
        *(uint4*)&As[0][rowA + 64][cc] = sQh1;
        *(uint4*)&As[1][rowA     ][cc] = sQl0;
        *(uint4*)&As[1][rowA + 64][cc] = sQl1;
        *(uint4*)&Bs[rowA     ][cc] = sK0;
        *(uint4*)&Bs[rowA + 64][cc] = sK1;
        __syncthreads();

        if (it < DD / BK - 1) {
            pQh0 += BK; pQh1 += BK; pQl0 += BK; pQl1 += BK; pK0 += BK; pK1 += BK;
            sQh0 = *(const uint4*)pQh0; sQh1 = *(const uint4*)pQh1;
            sQl0 = *(const uint4*)pQl0; sQl1 = *(const uint4*)pQl1;
            sK0  = *(const uint4*)pK0;  sK1  = *(const uint4*)pK1;
        }

#pragma unroll
        for (int ks = 0; ks < 2; ++ks) {
            const int k0 = ks * 16;
            uint32_t bf[4][2];
#pragma unroll
            for (int pr = 0; pr < 2; ++pr) {
                uint32_t r0, r1, r2, r3;
                uint32_t addr = bBase +
                    ((uint32_t)(wn * 32 + pr * 16 + bRow) * SKP + k0 + bKh) * 2;
                ldm_x4(r0, r1, r2, r3, addr);
                bf[pr * 2 + 0][0] = r0; bf[pr * 2 + 0][1] = r1;
                bf[pr * 2 + 1][0] = r2; bf[pr * 2 + 1][1] = r3;
            }
#pragma unroll
            for (int p = 0; p < 2; ++p) {
#pragma unroll
                for (int mt = 0; mt < 4; ++mt) {
                    uint32_t af[4];
                    uint32_t addr = aBase +
                        ((uint32_t)(p * BM * SKP) +
                         (uint32_t)(wm * 64 + mt * 16 + aRow) * SKP + k0 + aKh) * 2;
                    ldm_x4(af[0], af[1], af[2], af[3], addr);
#pragma unroll
                    for (int nt = 0; nt < 4; ++nt)
                        mma_bf16(acc[mt][nt], af, bf[nt]);
                }
            }
        }
    }

    float* Sz = S + (size_t)z * NN * NN;
#pragma unroll
    for (int mt = 0; mt < 4; ++mt) {
        const int r0 = ib + wm * 64 + mt * 16 + (lane >> 2);
#pragma unroll
        for (int nt = 0; nt < 4; ++nt) {
            const int c0 = jb + wn * 32 + nt * 8 + ((lane & 3) << 1);
            *(float2*)(Sz + (size_t)r0 * NN + c0) =
                make_float2(acc[mt][nt][0], acc[mt][nt][1]);
            *(float2*)(Sz + (size_t)(r0 + 8) * NN + c0) =
                make_float2(acc[mt][nt][2], acc[mt][nt][3]);
        }
    }
}

// ---------------------------------------------------------------------------
// softmax over keys (rows of S), fp32 in -> bf16 out
// ---------------------------------------------------------------------------
__global__ __launch_bounds__(256)
void softmax_kernel(const float* __restrict__ S, __nv_bfloat16* __restrict__ P)
{
    const int warp = threadIdx.x >> 5;
    const int lane = threadIdx.x & 31;
    const size_t row = (size_t)blockIdx.x * 8 + warp;
    const float* r = S + row * NN;
    __nv_bfloat16* p = P + row * NN;

    float4 v[8];
    float mx = -3.0e38f;
#pragma unroll
    for (int q = 0; q < 8; ++q) {
        v[q] = *(const float4*)(r + q * 128 + lane * 4);
        mx = fmaxf(mx, fmaxf(fmaxf(v[q].x, v[q].y), fmaxf(v[q].z, v[q].w)));
    }
#pragma unroll
    for (int o = 16; o > 0; o >>= 1)
        mx = fmaxf(mx, __shfl_xor_sync(0xffffffffu, mx, o));

    float sum = 0.f;
#pragma unroll
    for (int q = 0; q < 8; ++q) {
        v[q].x = __expf(v[q].x - mx); v[q].y = __expf(v[q].y - mx);
        v[q].z = __expf(v[q].z - mx); v[q].w = __expf(v[q].w - mx);
        sum += (v[q].x + v[q].y) + (v[q].z + v[q].w);
    }
#pragma unroll
    for (int o = 16; o > 0; o >>= 1)
        sum += __shfl_xor_sync(0xffffffffu, sum, o);

    const float inv = 1.0f / sum;
#pragma unroll
    for (int q = 0; q < 8; ++q) {
        __nv_bfloat162 u0 = __float22bfloat162_rn(make_float2(v[q].x * inv, v[q].y * inv));
        __nv_bfloat162 u1 = __float22bfloat162_rn(make_float2(v[q].z * inv, v[q].w * inv));
        __nv_bfloat162* dst = (__nv_bfloat162*)(p + q * 128 + lane * 4);
        dst[0] = u0; dst[1] = u1;
    }
}

// ---------------------------------------------------------------------------
// GEMM2: out[z][d][n] = sa * sum_m V[z][d][m] * P[z][n][m] + sb * YP[b][d][n]
// ---------------------------------------------------------------------------
__global__ __launch_bounds__(256)
void gemm_pv(const __nv_bfloat16* __restrict__ Vb, const __nv_bfloat16* __restrict__ P,
             float* __restrict__ Out, const float* __restrict__ gamma,
             const float* __restrict__ YP)
{
    __shared__ __align__(16) __nv_bfloat16 As[BM][SKP];   // V rows (d)
    __shared__ __align__(16) __nv_bfloat16 Bs[BN][SKP];   // P rows (n)

    const int z  = blockIdx.z;
    const int ib = blockIdx.y * BM;       // d-base
    const int jb = blockIdx.x * BN;       // n-base
    const int t  = threadIdx.x;
    const int lane = t & 31, warp = t >> 5;
    const int wm = warp >> 2, wn = warp & 3;

    const int rowA = t >> 2;
    const int cc   = (t & 3) << 3;

    const __nv_bfloat16* pV0 = Vb + (size_t)z * DVV * NN + (size_t)(ib + rowA) * NN + cc;
    const __nv_bfloat16* pV1 = pV0 + (size_t)64 * NN;
    const __nv_bfloat16* pP0 = P + (size_t)z * NN * NN + (size_t)(jb + rowA) * NN + cc;
    const __nv_bfloat16* pP1 = pP0 + (size_t)64 * NN;

    uint32_t aBase = (uint32_t)__cvta_generic_to_shared(&As[0][0]);
    uint32_t bBase = (uint32_t)__cvta_generic_to_shared(&Bs[0][0]);

    const int aRow = lane & 15;
    const int aKh  = (lane >> 4) << 3;
    const int bRow = ((lane >> 4) << 3) + (lane & 7);
    const int bKh  = ((lane >> 3) & 1) << 3;

    float acc[4][4][4] = {};

    uint4 sV0 = *(const uint4*)pV0, sV1 = *(const uint4*)pV1;
    uint4 sP0 = *(const uint4*)pP0, sP1 = *(const uint4*)pP1;

    for (int it = 0; it < NN / BK; ++it) {
        __syncthreads();
        *(uint4*)&As[rowA     ][cc] = sV0;
        *(uint4*)&As[rowA + 64][cc] = sV1;
        *(uint4*)&Bs[rowA     ][cc] = sP0;
        *(uint4*)&Bs[rowA + 64][cc] = sP1;
        __syncthreads();

        if (it < NN / BK - 1) {
            pV0 += BK; pV1 += BK; pP0 += BK; pP1 += BK;
            sV0 = *(const uint4*)pV0; sV1 = *(const uint4*)pV1;
            sP0 = *(const uint4*)pP0; sP1 = *(const uint4*)pP1;
        }

#pragma unroll
        for (int ks = 0; ks < 2; ++ks) {
            const int k0 = ks * 16;
            uint32_t bf[4][2];
#pragma unroll
            for (int pr = 0; pr < 2; ++pr) {
                uint32_t r0, r1, r2, r3;
                uint32_t addr = bBase +
                    ((uint32_t)(wn * 32 + pr * 16 + bRow) * SKP + k0 + bKh) * 2;
                ldm_x4(r0, r1, r2, r3, addr);
                bf[pr * 2 + 0][0] = r0; bf[pr * 2 + 0][1] = r1;
                bf[pr * 2 + 1][0] = r2; bf[pr * 2 + 1][1] = r3;
            }
#pragma unroll
            for (int mt = 0; mt < 4; ++mt) {
                uint32_t af[4];
                uint32_t addr = aBase +
                    ((uint32_t)(wm * 64 + mt * 16 + aRow) * SKP + k0 + aKh) * 2;
                ldm_x4(af[0], af[1], af[2], af[3], addr);
#pragma unroll
                for (int nt = 0; nt < 4; ++nt)
                    mma_bf16(acc[mt][nt], af, bf[nt]);
            }
        }
    }

    const int h = z & (HH - 1);
    const int b = z >> 3;
    const float g  = gamma[h];
    const float sa = g / (1.0f + g);
    const float sb = 1.0f / (1.0f + g);

#pragma unroll
    for (int mt = 0; mt < 4; ++mt) {
        const int d0 = ib + wm * 64 + mt * 16 + (lane >> 2);
#pragma unroll
        for (int nt = 0; nt < 4; ++nt) {
            const int c0 = jb + wn * 32 + nt * 8 + ((lane & 3) << 1);
#pragma unroll
            for (int half = 0; half < 2; ++half) {
                const int d = d0 + half * 8;
                float2 yv = *(const float2*)(YP + ((size_t)b * DVV + d) * NN + c0);
                float2 ov = make_float2(
                    sa * acc[mt][nt][half * 2 + 0] + sb * yv.x,
                    sa * acc[mt][nt][half * 2 + 1] + sb * yv.y);
                *(float2*)(Out + ((size_t)z * DVV + d) * NN + c0) = ov;
            }
        }
    }
}

// ---------------------------------------------------------------------------
extern "C" void kernel_launch(void* const* d_in, const int* in_sizes, int n_in,
                              void* d_out, int out_size)
{
    const float* x     = (const float*)d_in[0];
    const float* y     = (const float*)d_in[1];
    const float* Wq    = (const float*)d_in[2];
    const float* bq    = (const float*)d_in[3];
    const float* Wk    = (const float*)d_in[4];
    const float* bk    = (const float*)d_in[5];
    const float* Wv    = (const float*)d_in[6];
    const float* bv    = (const float*)d_in[7];
    const float* Wp    = (const float*)d_in[8];
    const float* gamma = (const float*)d_in[9];
    float* out = (float*)d_out;

    __nv_bfloat16 *Qh, *Ql, *Kb, *Vb, *P;
    float *YP, *S;
    cudaGetSymbolAddress((void**)&Qh, g_Qh);
    cudaGetSymbolAddress((void**)&Ql, g_Ql);
    cudaGetSymbolAddress((void**)&Kb, g_Kb);
    cudaGetSymbolAddress((void**)&Vb, g_Vb);
    cudaGetSymbolAddress((void**)&YP, g_YP);
    cudaGetSymbolAddress((void**)&S,  g_S);
    cudaGetSymbolAddress((void**)&P,  g_P);

    dim3 thr(256);

    proj_kernel<<<dim3(NN / TILE, (HH * DD)  / TILE, BB), thr>>>(Wq, bq, x, Qh, Ql, HH * DD, 0);
    proj_kernel<<<dim3(NN / TILE, (HH * DD)  / TILE, BB), thr>>>(Wk, bk, x, Kb, nullptr, HH * DD, 3);
    proj_kernel<<<dim3(NN / TILE, (HH * DVV) / TILE, BB), thr>>>(Wv, bv, y, Vb, nullptr, HH * DVV, 1);
    proj_kernel<<<dim3(NN / TILE, DVV / TILE, BB), thr>>>(Wp, nullptr, y, YP, nullptr, DVV, 2);

    gemm_qk<<<dim3(NN / BN, NN / BM, BHH), thr>>>(Qh, Ql, Kb, S);

    softmax_kernel<<<dim3(BHH * NN / 8), thr>>>(S, P);

    gemm_pv<<<dim3(NN / BN, DVV / BM, BHH), thr>>>(Vb, P, out, gamma, YP);
}

// round 3
// speedup vs baseline: 2.5964x; 1.1436x over previous
#include <cuda_runtime.h>
#include <cuda_bf16.h>
#include <cstdint>

#define BB   4
#define CC   256
#define NN   1024
#define HH   8
#define DD   256
#define DVV  256
#define BHH  32

// ---- proj tiling ----
#define TILE 64
#define KCH  16
#define LDP  68

// ---- flash tiling ----
#define IT   64      // queries per CTA
#define JT   128     // keys per j-tile
#define DCH  64      // d chunk in QK phase
#define QP   264     // Q smem pitch (bf16 elems)  -> 132 words, %32=4, conflict-free
#define KP   72      // K chunk pitch              -> 36 words  %32=4
#define VP   136     // V pitch                    -> 68 words  %32=4
#define PP   136     // P pitch

// smem byte offsets
#define SM_QH   0
#define SM_QL   33792
#define SM_KB0  67584
#define SM_KB1  86016
#define SM_VT   104448
#define SM_PS   174080
#define SM_RS   191488
#define SM_TOT  191744

// Scratch
__device__ __nv_bfloat16 g_Qh[BHH * NN * DD];
__device__ __nv_bfloat16 g_Ql[BHH * NN * DD];
__device__ __nv_bfloat16 g_Kb[BHH * NN * DD];
__device__ __nv_bfloat16 g_Vb[BHH * DVV * NN];
__device__ float         g_YP[BB * DVV * NN];

// ---------------------------------------------------------------------------
__device__ __forceinline__ void ldm_x4(uint32_t& r0, uint32_t& r1, uint32_t& r2,
                                       uint32_t& r3, uint32_t addr) {
    asm volatile("ldmatrix.sync.aligned.m8n8.x4.shared.b16 {%0,%1,%2,%3}, [%4];\n"
                 : "=r"(r0), "=r"(r1), "=r"(r2), "=r"(r3) : "r"(addr));
}
__device__ __forceinline__ void mma_bf16(float* c, const uint32_t* a, const uint32_t* b) {
    asm volatile("mma.sync.aligned.m16n8k16.row.col.f32.bf16.bf16.f32 "
                 "{%0,%1,%2,%3}, {%4,%5,%6,%7}, {%8,%9}, {%0,%1,%2,%3};\n"
                 : "+f"(c[0]), "+f"(c[1]), "+f"(c[2]), "+f"(c[3])
                 : "r"(a[0]), "r"(a[1]), "r"(a[2]), "r"(a[3]), "r"(b[0]), "r"(b[1]));
}
__device__ __forceinline__ void cpa16(uint32_t saddr, const void* gaddr) {
    asm volatile("cp.async.cg.shared.global [%0], [%1], 16;\n"
                 :: "r"(saddr), "l"(gaddr));
}
#define CPCOMMIT() asm volatile("cp.async.commit_group;\n" ::: "memory")
#define CPWAIT0()  asm volatile("cp.async.wait_group 0;\n" ::: "memory")

// ---------------------------------------------------------------------------
// Merged projection: all of Q(hi/lo), K, V, YP in one launch.
// y-blocks: [0,32) Q  [32,64) K  [64,96) V  [96,100) P
// ---------------------------------------------------------------------------
__global__ __launch_bounds__(256)
void proj_all(const float* __restrict__ x, const float* __restrict__ y,
              const float* __restrict__ Wq, const float* __restrict__ bq,
              const float* __restrict__ Wk, const float* __restrict__ bk,
              const float* __restrict__ Wv, const float* __restrict__ bvb,
              const float* __restrict__ Wp,
              __nv_bfloat16* __restrict__ Qh, __nv_bfloat16* __restrict__ Ql,
              __nv_bfloat16* __restrict__ Kb, __nv_bfloat16* __restrict__ Vb,
              float* __restrict__ YP)
{
    __shared__ float As[KCH][LDP];
    __shared__ float Bs[KCH][LDP];

    const int b  = blockIdx.z;
    const int yb = blockIdx.y;
    const int nb = blockIdx.x * TILE;
    const int t  = threadIdx.x;

    int mode, ob;
    const float *W, *bias, *X;
    if (yb < 32)       { mode = 0; ob = yb * TILE;        W = Wq; bias = bq;   X = x; }
    else if (yb < 64)  { mode = 3; ob = (yb - 32) * TILE; W = Wk; bias = bk;   X = x; }
    else if (yb < 96)  { mode = 1; ob = (yb - 64) * TILE; W = Wv; bias = bvb;  X = y; }
    else               { mode = 2; ob = (yb - 96) * TILE; W = Wp; bias = nullptr; X = y; }

    const int ali = t >> 2;
    const int alk = (t & 3) << 2;
    const int blk = t >> 4;
    const int bln = (t & 15) << 2;
    const int i0  = (t & 15) << 2;
    const int j0  = (t >> 4) << 2;

    const float* Xb = X + (size_t)b * CC * NN;
    float acc[4][4] = {};

    for (int kc = 0; kc < CC; kc += KCH) {
        float4 av = *(const float4*)(W  + (size_t)(ob + ali) * CC + kc + alk);
        float4 bv = *(const float4*)(Xb + (size_t)(kc + blk) * NN + nb + bln);
        __syncthreads();
        As[alk + 0][ali] = av.x; As[alk + 1][ali] = av.y;
        As[alk + 2][ali] = av.z; As[alk + 3][ali] = av.w;
        *(float4*)&Bs[blk][bln] = bv;
        __syncthreads();
#pragma unroll
        for (int k = 0; k < KCH; ++k) {
            float4 a  = *(const float4*)&As[k][i0];
            float4 b4 = *(const float4*)&Bs[k][j0];
            acc[0][0] += a.x * b4.x; acc[0][1] += a.x * b4.y;
            acc[0][2] += a.x * b4.z; acc[0][3] += a.x * b4.w;
            acc[1][0] += a.y * b4.x; acc[1][1] += a.y * b4.y;
            acc[1][2] += a.y * b4.z; acc[1][3] += a.y * b4.w;
            acc[2][0] += a.z * b4.x; acc[2][1] += a.z * b4.y;
            acc[2][2] += a.z * b4.z; acc[2][3] += a.z * b4.w;
            acc[3][0] += a.w * b4.x; acc[3][1] += a.w * b4.y;
            acc[3][2] += a.w * b4.z; acc[3][3] += a.w * b4.w;
        }
    }

    float bv0 = 0.f, bv1 = 0.f, bv2 = 0.f, bv3 = 0.f;
    if (bias) {
        bv0 = bias[ob + i0 + 0]; bv1 = bias[ob + i0 + 1];
        bv2 = bias[ob + i0 + 2]; bv3 = bias[ob + i0 + 3];
    }

    if (mode == 0 || mode == 3) {
        __nv_bfloat16* Oh = (mode == 0) ? Qh : Kb;
        const int og0  = ob + i0;
        const int h    = og0 / DD;
        const int dloc = og0 % DD;
        const size_t base = (size_t)(b * HH + h) * NN * DD;
#pragma unroll
        for (int jj = 0; jj < 4; ++jj) {
            const int n = nb + j0 + jj;
            float4 vv = make_float4(acc[0][jj] + bv0, acc[1][jj] + bv1,
                                    acc[2][jj] + bv2, acc[3][jj] + bv3);
            __nv_bfloat162 h0 = __float22bfloat162_rn(make_float2(vv.x, vv.y));
            __nv_bfloat162 h1 = __float22bfloat162_rn(make_float2(vv.z, vv.w));
            __nv_bfloat162* ph = (__nv_bfloat162*)(Oh + base + (size_t)n * DD + dloc);
            ph[0] = h0; ph[1] = h1;
            if (mode == 0) {
                __nv_bfloat162 l0 = __float22bfloat162_rn(make_float2(
                    vv.x - __bfloat162float(h0.x), vv.y - __bfloat162float(h0.y)));
                __nv_bfloat162 l1 = __float22bfloat162_rn(make_float2(
                    vv.z - __bfloat162float(h1.x), vv.w - __bfloat162float(h1.y)));
                __nv_bfloat162* pl = (__nv_bfloat162*)(Ql + base + (size_t)n * DD + dloc);
                pl[0] = l0; pl[1] = l1;
            }
        }
    } else if (mode == 1) {
#pragma unroll
        for (int ii = 0; ii < 4; ++ii) {
            const int og = ob + i0 + ii;
            const float bvi = (ii == 0) ? bv0 : (ii == 1) ? bv1 : (ii == 2) ? bv2 : bv3;
            __nv_bfloat162 v0 = __float22bfloat162_rn(
                make_float2(acc[ii][0] + bvi, acc[ii][1] + bvi));
            __nv_bfloat162 v1 = __float22bfloat162_rn(
                make_float2(acc[ii][2] + bvi, acc[ii][3] + bvi));
            __nv_bfloat162* po = (__nv_bfloat162*)(Vb + (size_t)(b * (HH * DVV) + og) * NN + nb + j0);
            po[0] = v0; po[1] = v1;
        }
    } else {
#pragma unroll
        for (int ii = 0; ii < 4; ++ii) {
            const int og = ob + i0 + ii;
            float4 vv = make_float4(acc[ii][0], acc[ii][1], acc[ii][2], acc[ii][3]);
            *(float4*)(YP + (size_t)(b * DVV + og) * NN + nb + j0) = vv;
        }
    }
}

// ---------------------------------------------------------------------------
// Fused attention: per (z, i-tile of 64 queries)
//   S = (Qh+Ql)·K^T  (2-pass bf16 MMA), P = exp(S) (no max-sub),
//   O += V·P^T (unnormalized), rowsum accum; epilogue: (g*O/rs + yp)/(1+g).
// ---------------------------------------------------------------------------
__global__ __launch_bounds__(256, 1)
void flash_attn(const __nv_bfloat16* __restrict__ Qhg, const __nv_bfloat16* __restrict__ Qlg,
                const __nv_bfloat16* __restrict__ Kg,  const __nv_bfloat16* __restrict__ Vg,
                const float* __restrict__ YP, const float* __restrict__ gamma,
                float* __restrict__ Out)
{
    extern __shared__ char sm[];
    __nv_bfloat16* qh = (__nv_bfloat16*)(sm + SM_QH);
    __nv_bfloat16* ql = (__nv_bfloat16*)(sm + SM_QL);
    __nv_bfloat16* ps = (__nv_bfloat16*)(sm + SM_PS);
    float* rsum = (float*)(sm + SM_RS);

    const uint32_t smBase = (uint32_t)__cvta_generic_to_shared(sm);
    const uint32_t qhU = smBase + SM_QH;
    const uint32_t qlU = smBase + SM_QL;
    const uint32_t kbU[2] = { smBase + SM_KB0, smBase + SM_KB1 };
    const uint32_t vtU = smBase + SM_VT;
    const uint32_t psU = smBase + SM_PS;

    const int z  = blockIdx.y;
    const int ib = blockIdx.x * IT;
    const int t  = threadIdx.x;
    const int lane = t & 31, warp = t >> 5;

    // QK warp layout: 2(m) x 4(n); PV warp layout: 4(d) x 2(i)
    const int wm  = warp >> 2, wn  = warp & 3;
    const int wmd = warp >> 1, wni = warp & 1;

    const int aRow = lane & 15;
    const int aKh  = (lane >> 4) << 3;
    const int bRow = ((lane >> 4) << 3) + (lane & 7);
    const int bKh  = ((lane >> 3) & 1) << 3;

    const size_t zq = (size_t)z * NN * DD;
    const size_t zv = (size_t)z * DVV * NN;

    // ---- load Q hi/lo tiles + zero rsum ----
    {
        const __nv_bfloat16* qgh = Qhg + zq + (size_t)ib * DD;
        const __nv_bfloat16* qgl = Qlg + zq + (size_t)ib * DD;
#pragma unroll
        for (int w = 0; w < 8; ++w) {
            const int c = t + w * 256;
            const int row = c >> 5, off = (c & 31) << 3;
            cpa16(qhU + (uint32_t)(row * QP + off) * 2, qgh + (size_t)row * DD + off);
            cpa16(qlU + (uint32_t)(row * QP + off) * 2, qgl + (size_t)row * DD + off);
        }
        CPCOMMIT();
        if (t < IT) rsum[t] = 0.f;
        CPWAIT0();
        __syncthreads();
    }

    float oacc[4][4][4] = {};   // [mtd][nti][e]  rows=d cols=i
    float rp[2][2] = {};        // rowsum partials (QK layout rows)

    for (int jt = 0; jt < NN / JT; ++jt) {
        // issue K chunk 0
        {
            const __nv_bfloat16* kg = Kg + zq + (size_t)jt * JT * DD;
#pragma unroll
            for (int w = 0; w < 4; ++w) {
                const int c = t + w * 256;
                const int row = c >> 3, off = (c & 7) << 3;
                cpa16(kbU[0] + (uint32_t)(row * KP + off) * 2, kg + (size_t)row * DD + off);
            }
            CPCOMMIT();
        }

        float sacc[2][4][4] = {};

        for (int dc = 0; dc < 4; ++dc) {
            CPWAIT0();
            __syncthreads();
            if (dc < 3) {
                const __nv_bfloat16* kg = Kg + zq + (size_t)jt * JT * DD + (dc + 1) * DCH;
#pragma unroll
                for (int w = 0; w < 4; ++w) {
                    const int c = t + w * 256;
                    const int row = c >> 3, off = (c & 7) << 3;
                    cpa16(kbU[(dc + 1) & 1] + (uint32_t)(row * KP + off) * 2,
                          kg + (size_t)row * DD + off);
                }
                CPCOMMIT();
            } else {
                const __nv_bfloat16* vg = Vg + zv + (size_t)jt * JT;
#pragma unroll
                for (int w = 0; w < 16; ++w) {
                    const int c = t + w * 256;
                    const int row = c >> 4, off = (c & 15) << 3;
                    cpa16(vtU + (uint32_t)(row * VP + off) * 2, vg + (size_t)row * NN + off);
                }
                CPCOMMIT();
            }

            const uint32_t kcur = kbU[dc & 1];
            const int dbase = dc * DCH;
#pragma unroll
            for (int k = 0; k < 4; ++k) {
                const int k0 = k * 16;
                uint32_t bf[4][2];
#pragma unroll
                for (int pr = 0; pr < 2; ++pr) {
                    uint32_t r0, r1, r2, r3;
                    ldm_x4(r0, r1, r2, r3,
                           kcur + (uint32_t)((wn * 32 + pr * 16 + bRow) * KP + k0 + bKh) * 2);
                    bf[pr * 2 + 0][0] = r0; bf[pr * 2 + 0][1] = r1;
                    bf[pr * 2 + 1][0] = r2; bf[pr * 2 + 1][1] = r3;
                }
#pragma unroll
                for (int mt = 0; mt < 2; ++mt) {
                    uint32_t af[4];
                    ldm_x4(af[0], af[1], af[2], af[3],
                           qhU + (uint32_t)((wm * 32 + mt * 16 + aRow) * QP + dbase + k0 + aKh) * 2);
#pragma unroll
                    for (int nt = 0; nt < 4; ++nt) mma_bf16(sacc[mt][nt], af, bf[nt]);
                    ldm_x4(af[0], af[1], af[2], af[3],
                           qlU + (uint32_t)((wm * 32 + mt * 16 + aRow) * QP + dbase + k0 + aKh) * 2);
#pragma unroll
                    for (int nt = 0; nt < 4; ++nt) mma_bf16(sacc[mt][nt], af, bf[nt]);
                }
            }
        }

        // exp + store P (bf16) to smem
#pragma unroll
        for (int mt = 0; mt < 2; ++mt) {
            const int r = wm * 32 + mt * 16 + (lane >> 2);
#pragma unroll
            for (int nt = 0; nt < 4; ++nt) {
                const float p0 = __expf(sacc[mt][nt][0]);
                const float p1 = __expf(sacc[mt][nt][1]);
                const float p2 = __expf(sacc[mt][nt][2]);
                const float p3 = __expf(sacc[mt][nt][3]);
                rp[mt][0] += p0 + p1;
                rp[mt][1] += p2 + p3;
                const int cj = wn * 32 + nt * 8 + ((lane & 3) << 1);
                *(__nv_bfloat162*)(ps + (size_t)r * PP + cj) =
                    __float22bfloat162_rn(make_float2(p0, p1));
                *(__nv_bfloat162*)(ps + (size_t)(r + 8) * PP + cj) =
                    __float22bfloat162_rn(make_float2(p2, p3));
            }
        }

        CPWAIT0();            // V tile done
        __syncthreads();      // Ps + V visible to all

        // PV: O[d][i] += V[d][m] * P[i][m]
#pragma unroll
        for (int k = 0; k < 8; ++k) {
            const int k0 = k * 16;
            uint32_t pb[4][2];
#pragma unroll
            for (int pr = 0; pr < 2; ++pr) {
                uint32_t r0, r1, r2, r3;
                ldm_x4(r0, r1, r2, r3,
                       psU + (uint32_t)((wni * 32 + pr * 16 + bRow) * PP + k0 + bKh) * 2);
                pb[pr * 2 + 0][0] = r0; pb[pr * 2 + 0][1] = r1;
                pb[pr * 2 + 1][0] = r2; pb[pr * 2 + 1][1] = r3;
            }
#pragma unroll
            for (int mtd = 0; mtd < 4; ++mtd) {
                uint32_t af[4];
                ldm_x4(af[0], af[1], af[2], af[3],
                       vtU + (uint32_t)((wmd * 64 + mtd * 16 + aRow) * VP + k0 + aKh) * 2);
#pragma unroll
                for (int nti = 0; nti < 4; ++nti) mma_bf16(oacc[mtd][nti], af, pb[nti]);
            }
        }
    }

    // ---- rowsum reduce ----
#pragma unroll
    for (int mt = 0; mt < 2; ++mt) {
#pragma unroll
        for (int hh = 0; hh < 2; ++hh) {
            float v = rp[mt][hh];
            v += __shfl_xor_sync(0xffffffffu, v, 1);
            v += __shfl_xor_sync(0xffffffffu, v, 2);
            if ((lane & 3) == 0)
                atomicAdd(&rsum[wm * 32 + mt * 16 + hh * 8 + (lane >> 2)], v);
        }
    }
    __syncthreads();

    // ---- epilogue ----
    const int h = z & (HH - 1);
    const int b = z >> 3;
    const float g  = gamma[h];
    const float sa = g / (1.0f + g);
    const float sb = 1.0f / (1.0f + g);

    float invv[4][2];
#pragma unroll
    for (int nti = 0; nti < 4; ++nti) {
        const int i0 = wni * 32 + nti * 8 + ((lane & 3) << 1);
        invv[nti][0] = 1.0f / rsum[i0];
        invv[nti][1] = 1.0f / rsum[i0 + 1];
    }

#pragma unroll
    for (int mtd = 0; mtd < 4; ++mtd) {
        const int d0 = wmd * 64 + mtd * 16 + (lane >> 2);
#pragma unroll
        for (int nti = 0; nti < 4; ++nti) {
            const int i0 = wni * 32 + nti * 8 + ((lane & 3) << 1);
            const float2 yv0 = *(const float2*)(YP + ((size_t)b * DVV + d0) * NN + ib + i0);
            const float2 yv1 = *(const float2*)(YP + ((size_t)b * DVV + d0 + 8) * NN + ib + i0);
            float2 o0, o1;
            o0.x = sa * (oacc[mtd][nti][0] * invv[nti][0]) + sb * yv0.x;
            o0.y = sa * (oacc[mtd][nti][1] * invv[nti][1]) + sb * yv0.y;
            o1.x = sa * (oacc[mtd][nti][2] * invv[nti][0]) + sb * yv1.x;
            o1.y = sa * (oacc[mtd][nti][3] * invv[nti][1]) + sb * yv1.y;
            *(float2*)(Out + ((size_t)z * DVV + d0) * NN + ib + i0) = o0;
            *(float2*)(Out + ((size_t)z * DVV + d0 + 8) * NN + ib + i0) = o1;
        }
    }
}

// ---------------------------------------------------------------------------
extern "C" void kernel_launch(void* const* d_in, const int* in_sizes, int n_in,
                              void* d_out, int out_size)
{
    const float* x     = (const float*)d_in[0];
    const float* y     = (const float*)d_in[1];
    const float* Wq    = (const float*)d_in[2];
    const float* bq    = (const float*)d_in[3];
    const float* Wk    = (const float*)d_in[4];
    const float* bk    = (const float*)d_in[5];
    const float* Wv    = (const float*)d_in[6];
    const float* bv    = (const float*)d_in[7];
    const float* Wp    = (const float*)d_in[8];
    const float* gamma = (const float*)d_in[9];
    float* out = (float*)d_out;

    __nv_bfloat16 *Qh, *Ql, *Kb, *Vb;
    float *YP;
    cudaGetSymbolAddress((void**)&Qh, g_Qh);
    cudaGetSymbolAddress((void**)&Ql, g_Ql);
    cudaGetSymbolAddress((void**)&Kb, g_Kb);
    cudaGetSymbolAddress((void**)&Vb, g_Vb);
    cudaGetSymbolAddress((void**)&YP, g_YP);

    cudaFuncSetAttribute(flash_attn, cudaFuncAttributeMaxDynamicSharedMemorySize, SM_TOT);

    proj_all<<<dim3(NN / TILE, 100, BB), 256>>>(x, y, Wq, bq, Wk, bk, Wv, bv, Wp,
                                                Qh, Ql, Kb, Vb, YP);

    flash_attn<<<dim3(NN / IT, BHH), 256, SM_TOT>>>(Qh, Ql, Kb, Vb, YP, gamma, out);
}